// round 14
// baseline (speedup 1.0000x reference)
#include <cuda_runtime.h>
#include <cuda_fp16.h>
#include <cstdint>

#define NNODES 100000
#define NEDGES 600000
#define DH 128
#define SCAN_CHUNK 1024
#define NSCAN_BLOCKS ((NNODES + SCAN_CHUNK - 1) / SCAN_CHUNK)   // 98
#define NREP 32   // replicated column-stat accumulators

// ---------------- scratch (static device memory; no allocations) -------------
__device__ __half g_h[(size_t)NNODES * DH];     // 25.6 MB (fp16 features)
__device__ __half g_agg16[(size_t)NNODES * DH]; // 25.6 MB (BN input, fp16)
__device__ float  g_dinv[NNODES];
__device__ int    g_deg[NNODES];                // 16B-aligned (device globals)
__device__ int    g_start[NNODES + 1];
__device__ int    g_cursor[NNODES];
__device__ int    g_src[NEDGES];
__device__ float  g_colsum_r[NREP][DH];
__device__ float  g_colsq_r[NREP][DH];
__device__ float  g_scale[DH];
__device__ float  g_shift[DH];
__device__ int    g_done;                       // agg1 block retirement counter

// ---------------- helpers ----------------------------------------------------
__device__ __forceinline__ uint32_t f2tf32(float f) {
    uint32_t r;
    asm("cvt.rna.tf32.f32 %0, %1;" : "=r"(r) : "f"(f));
    return r;
}

__device__ __forceinline__ void mma_tf32(float* c, const uint32_t* a, const uint32_t* b) {
    asm volatile("mma.sync.aligned.m16n8k8.row.col.f32.tf32.tf32.f32 "
        "{%0,%1,%2,%3}, {%4,%5,%6,%7}, {%8,%9}, {%0,%1,%2,%3};"
        : "+f"(c[0]), "+f"(c[1]), "+f"(c[2]), "+f"(c[3])
        : "r"(a[0]), "r"(a[1]), "r"(a[2]), "r"(a[3]), "r"(b[0]), "r"(b[1]));
}

// ---------------- count incoming degree (dst side) ----------------------------
__global__ void k_count(const int* __restrict__ ei) {
    int e4 = blockIdx.x * blockDim.x + threadIdx.x;
    if (e4 * 4 >= NEDGES) return;
    int4 d = ((const int4*)(ei + NEDGES))[e4];
    atomicAdd(&g_deg[d.x], 1);
    atomicAdd(&g_deg[d.y], 1);
    atomicAdd(&g_deg[d.z], 1);
    atomicAdd(&g_deg[d.w], 1);
}

// ---------------- merged scan: one kernel, 98 blocks x 1024 ------------------
// Block b: (1) block-reduce deg[0 .. b*1024) for its chunk prefix (int4 loads),
//          (2) warp-shuffle local scan of its own chunk,
//          (3) write start/cursor/dinv.
__global__ void k_scan() {
    __shared__ int wsum[32];
    __shared__ int s_prefix;
    int b = blockIdx.x;
    int t = threadIdx.x;
    int lane = t & 31;
    int wid = t >> 5;

    // phase 1: chunk prefix = sum of deg[0 .. b*1024)
    int psum = 0;
    {
        const int4* d4 = (const int4*)g_deg;
        int n4 = b * (SCAN_CHUNK / 4);          // b*256 int4s
        for (int j = t; j < n4; j += SCAN_CHUNK) {
            int4 v = d4[j];
            psum += v.x + v.y + v.z + v.w;
        }
#pragma unroll
        for (int off = 16; off > 0; off >>= 1)
            psum += __shfl_down_sync(0xFFFFFFFFu, psum, off);
        if (lane == 0) wsum[wid] = psum;
    }
    __syncthreads();
    if (wid == 0) {
        int s = wsum[lane];
#pragma unroll
        for (int off = 16; off > 0; off >>= 1)
            s += __shfl_down_sync(0xFFFFFFFFu, s, off);
        if (lane == 0) s_prefix = s;
    }
    __syncthreads();
    int prefix = s_prefix;
    __syncthreads();   // wsum reused below

    // phase 2: local warp-shuffle scan of chunk b
    int i = b * SCAN_CHUNK + t;
    int v = (i < NNODES) ? g_deg[i] : 0;
    int x = v;
#pragma unroll
    for (int off = 1; off < 32; off <<= 1) {
        int u = __shfl_up_sync(0xFFFFFFFFu, x, off);
        if (lane >= off) x += u;
    }
    if (lane == 31) wsum[wid] = x;
    __syncthreads();
    if (wid == 0) {
        int s = wsum[lane];
#pragma unroll
        for (int off = 1; off < 32; off <<= 1) {
            int u = __shfl_up_sync(0xFFFFFFFFu, s, off);
            if (lane >= off) s += u;
        }
        wsum[lane] = s;
    }
    __syncthreads();
    int base = (wid > 0) ? wsum[wid - 1] : 0;
    int excl = prefix + base + x - v;

    if (i < NNODES) {
        g_start[i] = excl;
        g_cursor[i] = excl;
        g_dinv[i] = rsqrtf((float)(v + 1));
    }
    if (i == 0) g_start[NNODES] = NEDGES;
}

// ---------------- scatter edges into CSR (by dst) ----------------------------
__global__ void k_buildcsr(const int* __restrict__ ei) {
    int e = blockIdx.x * blockDim.x + threadIdx.x;
    if (e >= NEDGES) return;
    int src = ei[e];
    int dst = ei[NEDGES + e];
    int pos = atomicAdd(&g_cursor[dst], 1);
    g_src[pos] = src;
}

// ---------------- TF32 tensor-core GEMM: C[M,128](fp16) = op(A) @ B ----------
#define AS_STRIDE 20
#define BS_STRIDE 136

template <typename AT, bool FUSE_BN>
__device__ __forceinline__ void gemm_load_regs(
    const AT* __restrict__ A, const float* __restrict__ B, int M,
    int rowBase, int aRow, int aCol, int bRow, int bCol, int k0,
    float4& av0, float4& av1, float4& bv0, float4& bv1) {
    int gr = rowBase + aRow;
    av0 = make_float4(0.f, 0.f, 0.f, 0.f); av1 = av0;
    if (gr < M) {
        const AT* ap = A + (size_t)gr * 128 + k0 + aCol;
        if (sizeof(AT) == 4) {
            av0 = *(const float4*)(ap);
            av1 = *(const float4*)((const float*)ap + 4);
        } else {
            uint4 u = *(const uint4*)(ap);   // 8 halves
            float2 p0 = __half22float2(*(__half2*)&u.x);
            float2 p1 = __half22float2(*(__half2*)&u.y);
            float2 p2 = __half22float2(*(__half2*)&u.z);
            float2 p3 = __half22float2(*(__half2*)&u.w);
            av0 = make_float4(p0.x, p0.y, p1.x, p1.y);
            av1 = make_float4(p2.x, p2.y, p3.x, p3.y);
        }
    }
    if (FUSE_BN) {
        int c = k0 + aCol;
        float4 sc0 = *(const float4*)&g_scale[c];
        float4 sc1 = *(const float4*)&g_scale[c + 4];
        float4 sh0 = *(const float4*)&g_shift[c];
        float4 sh1 = *(const float4*)&g_shift[c + 4];
        av0.x = fmaxf(fmaf(av0.x, sc0.x, sh0.x), 0.f);
        av0.y = fmaxf(fmaf(av0.y, sc0.y, sh0.y), 0.f);
        av0.z = fmaxf(fmaf(av0.z, sc0.z, sh0.z), 0.f);
        av0.w = fmaxf(fmaf(av0.w, sc0.w, sh0.w), 0.f);
        av1.x = fmaxf(fmaf(av1.x, sc1.x, sh1.x), 0.f);
        av1.y = fmaxf(fmaf(av1.y, sc1.y, sh1.y), 0.f);
        av1.z = fmaxf(fmaf(av1.z, sc1.z, sh1.z), 0.f);
        av1.w = fmaxf(fmaf(av1.w, sc1.w, sh1.w), 0.f);
    }
    const float* bp = B + (size_t)(k0 + bRow) * 128 + bCol;
    bv0 = *(const float4*)(bp);
    bv1 = *(const float4*)(bp + 4);
}

__device__ __forceinline__ void gemm_store_smem(
    uint32_t (*As)[AS_STRIDE], uint32_t (*Bs)[BS_STRIDE],
    int aRow, int aCol, int bRow, int bCol,
    const float4& av0, const float4& av1, const float4& bv0, const float4& bv1) {
    *(uint4*)&As[aRow][aCol]     = make_uint4(f2tf32(av0.x), f2tf32(av0.y), f2tf32(av0.z), f2tf32(av0.w));
    *(uint4*)&As[aRow][aCol + 4] = make_uint4(f2tf32(av1.x), f2tf32(av1.y), f2tf32(av1.z), f2tf32(av1.w));
    *(uint4*)&Bs[bRow][bCol]     = make_uint4(f2tf32(bv0.x), f2tf32(bv0.y), f2tf32(bv0.z), f2tf32(bv0.w));
    *(uint4*)&Bs[bRow][bCol + 4] = make_uint4(f2tf32(bv1.x), f2tf32(bv1.y), f2tf32(bv1.z), f2tf32(bv1.w));
}

template <typename AT, bool FUSE_BN>
__global__ void __launch_bounds__(256, 2)
k_gemm(const AT* __restrict__ A, const float* __restrict__ B,
       __half* __restrict__ C, int M) {
    __shared__ uint32_t As[2][128][AS_STRIDE];
    __shared__ uint32_t Bs[2][16][BS_STRIDE];

    int tid = threadIdx.x;
    int lane = tid & 31;
    int warp = tid >> 5;
    int gid = lane >> 2;
    int tig = lane & 3;
    int wm = warp & 3;
    int wn = warp >> 2;
    int rowBase = blockIdx.x * 128;

    float acc[2][8][4];
#pragma unroll
    for (int i = 0; i < 2; i++)
#pragma unroll
        for (int j = 0; j < 8; j++)
#pragma unroll
            for (int q = 0; q < 4; q++) acc[i][j][q] = 0.f;

    int aRow = tid >> 1;
    int aCol = (tid & 1) * 8;
    int bRow = tid >> 4;
    int bCol = (tid & 15) * 8;

    float4 av0, av1, bv0, bv1;
    gemm_load_regs<AT, FUSE_BN>(A, B, M, rowBase, aRow, aCol, bRow, bCol, 0, av0, av1, bv0, bv1);
    gemm_store_smem(As[0], Bs[0], aRow, aCol, bRow, bCol, av0, av1, bv0, bv1);
    __syncthreads();

#pragma unroll
    for (int c = 0; c < 8; c++) {
        int cur = c & 1;
        if (c < 7)
            gemm_load_regs<AT, FUSE_BN>(A, B, M, rowBase, aRow, aCol, bRow, bCol,
                                        (c + 1) * 16, av0, av1, bv0, bv1);
#pragma unroll
        for (int ks = 0; ks < 16; ks += 8) {
            uint32_t a[2][4], b[8][2];
#pragma unroll
            for (int i = 0; i < 2; i++) {
                int mb = wm * 32 + i * 16;
                a[i][0] = As[cur][mb + gid][ks + tig];
                a[i][1] = As[cur][mb + gid + 8][ks + tig];
                a[i][2] = As[cur][mb + gid][ks + tig + 4];
                a[i][3] = As[cur][mb + gid + 8][ks + tig + 4];
            }
#pragma unroll
            for (int j = 0; j < 8; j++) {
                int nb = wn * 64 + j * 8;
                b[j][0] = Bs[cur][ks + tig][nb + gid];
                b[j][1] = Bs[cur][ks + tig + 4][nb + gid];
            }
#pragma unroll
            for (int i = 0; i < 2; i++)
#pragma unroll
                for (int j = 0; j < 8; j++) mma_tf32(acc[i][j], a[i], b[j]);
        }
        if (c < 7)
            gemm_store_smem(As[cur ^ 1], Bs[cur ^ 1], aRow, aCol, bRow, bCol, av0, av1, bv0, bv1);
        __syncthreads();
    }

    // epilogue: fp32 acc -> fp16 store
#pragma unroll
    for (int i = 0; i < 2; i++) {
        int r0 = rowBase + wm * 32 + i * 16 + gid;
        int r1 = r0 + 8;
#pragma unroll
        for (int j = 0; j < 8; j++) {
            int col = wn * 64 + j * 8 + tig * 2;
            if (r0 < M) *(__half2*)(C + (size_t)r0 * 128 + col) =
                __floats2half2_rn(acc[i][j][0], acc[i][j][1]);
            if (r1 < M) *(__half2*)(C + (size_t)r1 * 128 + col) =
                __floats2half2_rn(acc[i][j][2], acc[i][j][3]);
        }
    }
}

// ---------------- gather aggregation (fp16 features): warp per node ----------
// out[n] = dinv[n]*( h[n]*dinv[n] + sum_{s in in(n)} h[s]*dinv[s] ) + bias
// (round-10 proven unroll-2 loop). STATS: column stats + last retiring block
// computes BN scale/shift (folded bnstats).
template <bool STATS, typename OutT>
__global__ void k_agg(const __half* __restrict__ h, const float* __restrict__ bias,
                      OutT* __restrict__ out,
                      const float* __restrict__ gamma, const float* __restrict__ beta) {
    __shared__ float s_sum[8][DH];
    __shared__ float s_sq[8][DH];
    __shared__ int s_last;
    int warp = threadIdx.x >> 5;
    int lane = threadIdx.x & 31;
    int n = blockIdx.x * 8 + warp;
    float4 acc = make_float4(0.f, 0.f, 0.f, 0.f);
    if (n < NNODES) {
        float di = g_dinv[n];
        {
            uint2 u = ((const uint2*)(h + (size_t)n * DH))[lane];
            float2 fa = __half22float2(*(__half2*)&u.x);
            float2 fb = __half22float2(*(__half2*)&u.y);
            acc.x = fa.x * di; acc.y = fa.y * di;
            acc.z = fb.x * di; acc.w = fb.y * di;
        }
        int beg = g_start[n], end = g_start[n + 1];
        int idx = beg;
        for (; idx + 2 <= end; idx += 2) {
            int s0 = g_src[idx], s1 = g_src[idx + 1];
            float w0 = g_dinv[s0], w1 = g_dinv[s1];
            uint2 u0 = ((const uint2*)(h + (size_t)s0 * DH))[lane];
            uint2 u1 = ((const uint2*)(h + (size_t)s1 * DH))[lane];
            float2 a0 = __half22float2(*(__half2*)&u0.x);
            float2 b0 = __half22float2(*(__half2*)&u0.y);
            float2 a1 = __half22float2(*(__half2*)&u1.x);
            float2 b1 = __half22float2(*(__half2*)&u1.y);
            acc.x = fmaf(a0.x, w0, acc.x); acc.y = fmaf(a0.y, w0, acc.y);
            acc.z = fmaf(b0.x, w0, acc.z); acc.w = fmaf(b0.y, w0, acc.w);
            acc.x = fmaf(a1.x, w1, acc.x); acc.y = fmaf(a1.y, w1, acc.y);
            acc.z = fmaf(b1.x, w1, acc.z); acc.w = fmaf(b1.y, w1, acc.w);
        }
        if (idx < end) {
            int s0 = g_src[idx];
            float w0 = g_dinv[s0];
            uint2 u0 = ((const uint2*)(h + (size_t)s0 * DH))[lane];
            float2 a0 = __half22float2(*(__half2*)&u0.x);
            float2 b0 = __half22float2(*(__half2*)&u0.y);
            acc.x = fmaf(a0.x, w0, acc.x); acc.y = fmaf(a0.y, w0, acc.y);
            acc.z = fmaf(b0.x, w0, acc.z); acc.w = fmaf(b0.y, w0, acc.w);
        }
        float4 bv = ((const float4*)bias)[lane];
        acc.x = fmaf(acc.x, di, bv.x);
        acc.y = fmaf(acc.y, di, bv.y);
        acc.z = fmaf(acc.z, di, bv.z);
        acc.w = fmaf(acc.w, di, bv.w);
        if (sizeof(OutT) == 4) {
            ((float4*)(out + (size_t)n * DH))[lane] = acc;
        } else {
            uint2 st;
            *(__half2*)&st.x = __floats2half2_rn(acc.x, acc.y);
            *(__half2*)&st.y = __floats2half2_rn(acc.z, acc.w);
            ((uint2*)(out + (size_t)n * DH))[lane] = st;
        }
    }
    if (STATS) {
        int c = lane * 4;
        s_sum[warp][c + 0] = acc.x; s_sum[warp][c + 1] = acc.y;
        s_sum[warp][c + 2] = acc.z; s_sum[warp][c + 3] = acc.w;
        s_sq[warp][c + 0] = acc.x * acc.x; s_sq[warp][c + 1] = acc.y * acc.y;
        s_sq[warp][c + 2] = acc.z * acc.z; s_sq[warp][c + 3] = acc.w * acc.w;
        __syncthreads();
        int t = threadIdx.x;
        int rep = blockIdx.x & (NREP - 1);
        if (t < DH) {
            float s = 0.f;
#pragma unroll
            for (int w = 0; w < 8; w++) s += s_sum[w][t];
            atomicAdd(&g_colsum_r[rep][t], s);
        } else {
            int c2 = t - DH;
            float s = 0.f;
#pragma unroll
            for (int w = 0; w < 8; w++) s += s_sq[w][c2];
            atomicAdd(&g_colsq_r[rep][c2], s);
        }
        // last retiring block computes BN scale/shift (folded k_bnstats)
        if (t == 0) {
            __threadfence();
            int v = atomicAdd(&g_done, 1);
            s_last = (v == gridDim.x - 1) ? 1 : 0;
        }
        __syncthreads();
        if (s_last && t < DH) {
            float sum = 0.f, sq = 0.f;
#pragma unroll
            for (int r = 0; r < NREP; r++) { sum += g_colsum_r[r][t]; sq += g_colsq_r[r][t]; }
            float mean = sum * (1.0f / NNODES);
            float var = sq * (1.0f / NNODES) - mean * mean;
            float inv = rsqrtf(var + 1e-5f);
            float sc = gamma[t] * inv;
            g_scale[t] = sc;
            g_shift[t] = beta[t] - mean * sc;
        }
    }
}

// ---------------- launch -----------------------------------------------------
extern "C" void kernel_launch(void* const* d_in, const int* in_sizes, int n_in,
                              void* d_out, int out_size) {
    const float* x     = (const float*)d_in[0];
    const int*   ei    = (const int*)d_in[1];
    const float* W1    = (const float*)d_in[2];
    const float* b1    = (const float*)d_in[3];
    const float* gamma = (const float*)d_in[4];
    const float* beta  = (const float*)d_in[5];
    const float* W2    = (const float*)d_in[6];
    const float* b2    = (const float*)d_in[7];
    float*       out   = (float*)d_out;

    __half* h   = nullptr; cudaGetSymbolAddress((void**)&h,   g_h);
    __half* agg = nullptr; cudaGetSymbolAddress((void**)&agg, g_agg16);
    void* p_deg = nullptr; cudaGetSymbolAddress(&p_deg, g_deg);
    void* p_cs  = nullptr; cudaGetSymbolAddress(&p_cs,  g_colsum_r);
    void* p_cq  = nullptr; cudaGetSymbolAddress(&p_cq,  g_colsq_r);
    void* p_dn  = nullptr; cudaGetSymbolAddress(&p_dn,  g_done);

    static cudaStream_t s2 = nullptr;
    static cudaEvent_t ev_fork = nullptr, ev_join = nullptr;
    if (s2 == nullptr) {
        cudaStreamCreateWithFlags(&s2, cudaStreamNonBlocking);
        cudaEventCreateWithFlags(&ev_fork, cudaEventDisableTiming);
        cudaEventCreateWithFlags(&ev_join, cudaEventDisableTiming);
    }

    // fork: CSR build (depends only on edge_index) concurrent with GEMM1
    cudaEventRecord(ev_fork, 0);
    cudaStreamWaitEvent(s2, ev_fork, 0);

    // zero scratch via memset nodes (no kernel-launch ramp)
    cudaMemsetAsync(p_deg, 0, NNODES * sizeof(int), s2);
    cudaMemsetAsync(p_cs,  0, NREP * DH * sizeof(float), s2);
    cudaMemsetAsync(p_cq,  0, NREP * DH * sizeof(float), s2);
    cudaMemsetAsync(p_dn,  0, sizeof(int), s2);

    k_count<<<(NEDGES / 4 + 255) / 256, 256, 0, s2>>>(ei);
    k_scan<<<NSCAN_BLOCKS, SCAN_CHUNK, 0, s2>>>();
    k_buildcsr<<<(NEDGES + 255) / 256, 256, 0, s2>>>(ei);

    k_gemm<float, false><<<(NNODES + 127) / 128, 256>>>(x, W1, h, NNODES);

    cudaEventRecord(ev_join, s2);
    cudaStreamWaitEvent(0, ev_join, 0);

    // layer 1: aggregate(+colstats, fp16 out, BN params by last block)
    k_agg<true, __half><<<(NNODES + 7) / 8, 256>>>(h, b1, agg, gamma, beta);

    // layer 2: GEMM(tf32, fused BN+ReLU on fp16 A) -> aggregate -> d_out
    k_gemm<__half, true><<<(NNODES + 127) / 128, 256>>>(agg, W2, h, NNODES);
    k_agg<false, float><<<(NNODES + 7) / 8, 256>>>(h, b2, out, nullptr, nullptr);
}

// round 15
// speedup vs baseline: 1.2300x; 1.2300x over previous
#include <cuda_runtime.h>
#include <cuda_fp16.h>
#include <cstdint>

#define NNODES 100000
#define NEDGES 600000
#define DH 128
#define SCAN_CHUNK 1024
#define NSCAN_BLOCKS ((NNODES + SCAN_CHUNK - 1) / SCAN_CHUNK)   // 98
#define NREP 32

// ---------------- scratch (static device memory; no allocations) -------------
__device__ __half g_h[(size_t)NNODES * DH];     // 25.6 MB (fp16 features)
__device__ __half g_agg16[(size_t)NNODES * DH]; // 25.6 MB (BN input, fp16)
__device__ __half g_w1t[DH * DH];               // W1^T fp16 [n][k]
__device__ __half g_w2t[DH * DH];               // W2^T fp16 [n][k]
__device__ float  g_dinv[NNODES];
__device__ int    g_deg[NNODES];
__device__ int    g_start[NNODES + 1];
__device__ int    g_cursor[NNODES];
__device__ int    g_src[NEDGES];
__device__ int    g_blocksums[NSCAN_BLOCKS];
__device__ float  g_colsum_r[NREP][DH];
__device__ float  g_colsq_r[NREP][DH];
__device__ float  g_scale[DH];
__device__ float  g_shift[DH];

// ---------------- helpers ----------------------------------------------------
__device__ __forceinline__ void mma_f16(float* c, const uint32_t* a, const uint32_t* b) {
    asm volatile("mma.sync.aligned.m16n8k16.row.col.f32.f16.f16.f32 "
        "{%0,%1,%2,%3}, {%4,%5,%6,%7}, {%8,%9}, {%0,%1,%2,%3};"
        : "+f"(c[0]), "+f"(c[1]), "+f"(c[2]), "+f"(c[3])
        : "r"(a[0]), "r"(a[1]), "r"(a[2]), "r"(a[3]), "r"(b[0]), "r"(b[1]));
}

// ---------------- init: zero deg + replicated column stats --------------------
__global__ void k_init() {
    int i = blockIdx.x * blockDim.x + threadIdx.x;
    if (i < NNODES) g_deg[i] = 0;
    if (i < NREP * DH) {
        ((float*)g_colsum_r)[i] = 0.f;
        ((float*)g_colsq_r)[i] = 0.f;
    }
}

// ---------------- weight prep: fp32 [k][n] -> fp16 transposed [n][k] ----------
__global__ void k_wprep(const float* __restrict__ W1, const float* __restrict__ W2) {
    int i = blockIdx.x * blockDim.x + threadIdx.x;   // 16384
    if (i >= DH * DH) return;
    int k = i >> 7, n = i & 127;
    g_w1t[n * DH + k] = __float2half(W1[i]);
    g_w2t[n * DH + k] = __float2half(W2[i]);
}

// ---------------- count incoming degree (dst side) ----------------------------
__global__ void k_count(const int* __restrict__ ei) {
    int e4 = blockIdx.x * blockDim.x + threadIdx.x;
    if (e4 * 4 >= NEDGES) return;
    int4 d = ((const int4*)(ei + NEDGES))[e4];
    atomicAdd(&g_deg[d.x], 1);
    atomicAdd(&g_deg[d.y], 1);
    atomicAdd(&g_deg[d.z], 1);
    atomicAdd(&g_deg[d.w], 1);
}

// ---------------- block-wise scan of deg (warp-shuffle) ----------------------
__global__ void k_scan1() {
    __shared__ int wsum[32];
    int i = blockIdx.x * SCAN_CHUNK + threadIdx.x;
    int v = (i < NNODES) ? g_deg[i] : 0;
    int lane = threadIdx.x & 31;
    int wid = threadIdx.x >> 5;
    int x = v;
#pragma unroll
    for (int off = 1; off < 32; off <<= 1) {
        int t = __shfl_up_sync(0xFFFFFFFFu, x, off);
        if (lane >= off) x += t;
    }
    if (lane == 31) wsum[wid] = x;
    __syncthreads();
    if (wid == 0) {
        int s = wsum[lane];
#pragma unroll
        for (int off = 1; off < 32; off <<= 1) {
            int t = __shfl_up_sync(0xFFFFFFFFu, s, off);
            if (lane >= off) s += t;
        }
        wsum[lane] = s;
    }
    __syncthreads();
    int base = (wid > 0) ? wsum[wid - 1] : 0;
    int incl = base + x;
    if (i < NNODES) g_start[i] = incl - v;
    if (threadIdx.x == SCAN_CHUNK - 1) g_blocksums[blockIdx.x] = incl;
}

// ---------------- finalize offsets ------------------------------------------
__global__ void k_scan3() {
    __shared__ int excl[128];
    int t = threadIdx.x;
    if (t < 128) {
        int v = (t < NSCAN_BLOCKS) ? g_blocksums[t] : 0;
        excl[t] = v;
    }
    __syncthreads();
    if (t < 128) {
        for (int off = 1; off < 128; off <<= 1) {
            int u = (t >= off) ? excl[t - off] : 0;
            __syncthreads();
            excl[t] += u;
            __syncthreads();
        }
        int v = (t < NSCAN_BLOCKS) ? g_blocksums[t] : 0;
        excl[t] -= v;
    } else {
        for (int off = 1; off < 128; off <<= 1) { __syncthreads(); __syncthreads(); }
    }
    __syncthreads();
    int i = blockIdx.x * blockDim.x + t;
    if (i < NNODES) {
        int st = g_start[i] + excl[i >> 10];
        g_start[i] = st;
        g_cursor[i] = st;
        g_dinv[i] = rsqrtf((float)(g_deg[i] + 1));
    }
    if (i == 0) g_start[NNODES] = NEDGES;
}

// ---------------- scatter edges into CSR (by dst) ----------------------------
__global__ void k_buildcsr(const int* __restrict__ ei) {
    int e = blockIdx.x * blockDim.x + threadIdx.x;
    if (e >= NEDGES) return;
    int src = ei[e];
    int dst = ei[NEDGES + e];
    int pos = atomicAdd(&g_cursor[dst], 1);
    g_src[pos] = src;
}

// ---------------- fp16 HMMA GEMM: C[M,128](fp16) = op(A) @ W -----------------
// 128x128 block tile, 8 warps 4(M)x2(N), warp tile 32x64, mma m16n8k16.
// A smem: [m][k] as half2-words; B smem: [n][k] as half2-words (W pre-transposed
// fp16). Row stride 12 words => all fragment LDS.32 are conflict-free.
// FUSE_BN: y = relu(a*scale+shift) applied to A on load.
#define FSTRIDE 12

template <typename AT, bool FUSE_BN>
__device__ __forceinline__ void gemm_load_regs(
    const AT* __restrict__ A, const __half* __restrict__ Wt, int M,
    int rowBase, int aRow, int aP, int bRow, int bP, int k0,
    uint4& apk, uint4& bpk) {
    int gr = rowBase + aRow;
    float f[8];
    if (gr < M) {
        if (sizeof(AT) == 4) {
            const float* ap = (const float*)A + (size_t)gr * 128 + k0 + aP * 2;
            float4 v0 = *(const float4*)(ap);
            float4 v1 = *(const float4*)(ap + 4);
            f[0] = v0.x; f[1] = v0.y; f[2] = v0.z; f[3] = v0.w;
            f[4] = v1.x; f[5] = v1.y; f[6] = v1.z; f[7] = v1.w;
        } else {
            const __half* ap = (const __half*)A + (size_t)gr * 128 + k0 + aP * 2;
            uint4 u = *(const uint4*)(ap);
            float2 p0 = __half22float2(*(__half2*)&u.x);
            float2 p1 = __half22float2(*(__half2*)&u.y);
            float2 p2 = __half22float2(*(__half2*)&u.z);
            float2 p3 = __half22float2(*(__half2*)&u.w);
            f[0] = p0.x; f[1] = p0.y; f[2] = p1.x; f[3] = p1.y;
            f[4] = p2.x; f[5] = p2.y; f[6] = p3.x; f[7] = p3.y;
        }
    } else {
#pragma unroll
        for (int q = 0; q < 8; q++) f[q] = 0.f;
    }
    if (FUSE_BN) {
        int c = k0 + aP * 2;
#pragma unroll
        for (int q = 0; q < 8; q++)
            f[q] = fmaxf(fmaf(f[q], g_scale[c + q], g_shift[c + q]), 0.f);
    }
    *(__half2*)&apk.x = __floats2half2_rn(f[0], f[1]);
    *(__half2*)&apk.y = __floats2half2_rn(f[2], f[3]);
    *(__half2*)&apk.z = __floats2half2_rn(f[4], f[5]);
    *(__half2*)&apk.w = __floats2half2_rn(f[6], f[7]);
    // B: Wt[n][k] fp16 row-major; this thread covers n=bRow, halves k0+bP*2..+7
    bpk = *(const uint4*)(Wt + (size_t)bRow * DH + k0 + bP * 2);
}

__device__ __forceinline__ void gemm_store_smem(
    uint32_t (*As)[FSTRIDE], uint32_t (*Bs)[FSTRIDE],
    int aRow, int aP, int bRow, int bP, const uint4& apk, const uint4& bpk) {
    *(uint4*)&As[aRow][aP] = apk;
    *(uint4*)&Bs[bRow][bP] = bpk;
}

template <typename AT, bool FUSE_BN>
__global__ void __launch_bounds__(256, 2)
k_gemm(const AT* __restrict__ A, const __half* __restrict__ Wt,
       __half* __restrict__ C, int M) {
    __shared__ uint32_t As[2][128][FSTRIDE];   // [buf][m][k-half2], 8 of 12 used
    __shared__ uint32_t Bs[2][128][FSTRIDE];   // [buf][n][k-half2]

    int tid = threadIdx.x;
    int lane = tid & 31;
    int warp = tid >> 5;
    int gid = lane >> 2;     // 0..7
    int tig = lane & 3;      // 0..3
    int wm = warp & 3;       // M warp 0..3
    int wn = warp >> 2;      // N warp 0..1
    int rowBase = blockIdx.x * 128;

    float acc[2][8][4];
#pragma unroll
    for (int i = 0; i < 2; i++)
#pragma unroll
        for (int j = 0; j < 8; j++)
#pragma unroll
            for (int q = 0; q < 4; q++) acc[i][j][q] = 0.f;

    int aRow = tid >> 1;          // 0..127 (m)
    int aP   = (tid & 1) * 4;     // half2-word 0 or 4
    int bRow = tid >> 1;          // 0..127 (n)
    int bP   = (tid & 1) * 4;

    uint4 apk, bpk;
    gemm_load_regs<AT, FUSE_BN>(A, Wt, M, rowBase, aRow, aP, bRow, bP, 0, apk, bpk);
    gemm_store_smem(As[0], Bs[0], aRow, aP, bRow, bP, apk, bpk);
    __syncthreads();

#pragma unroll
    for (int c = 0; c < 8; c++) {          // 8 chunks of k16
        int cur = c & 1;
        if (c < 7)
            gemm_load_regs<AT, FUSE_BN>(A, Wt, M, rowBase, aRow, aP, bRow, bP,
                                        (c + 1) * 16, apk, bpk);
        {
            uint32_t a[2][4], b[8][2];
#pragma unroll
            for (int i = 0; i < 2; i++) {
                int mb = wm * 32 + i * 16;
                a[i][0] = As[cur][mb + gid][tig];
                a[i][1] = As[cur][mb + gid + 8][tig];
                a[i][2] = As[cur][mb + gid][tig + 4];
                a[i][3] = As[cur][mb + gid + 8][tig + 4];
            }
#pragma unroll
            for (int j = 0; j < 8; j++) {
                int nb = wn * 64 + j * 8;
                b[j][0] = Bs[cur][nb + gid][tig];
                b[j][1] = Bs[cur][nb + gid][tig + 4];
            }
#pragma unroll
            for (int i = 0; i < 2; i++)
#pragma unroll
                for (int j = 0; j < 8; j++) mma_f16(acc[i][j], a[i], b[j]);
        }
        if (c < 7)
            gemm_store_smem(As[cur ^ 1], Bs[cur ^ 1], aRow, aP, bRow, bP, apk, bpk);
        __syncthreads();
    }

    // epilogue: fp32 acc -> fp16 store (same fragment layout as tf32 path)
#pragma unroll
    for (int i = 0; i < 2; i++) {
        int r0 = rowBase + wm * 32 + i * 16 + gid;
        int r1 = r0 + 8;
#pragma unroll
        for (int j = 0; j < 8; j++) {
            int col = wn * 64 + j * 8 + tig * 2;
            if (r0 < M) *(__half2*)(C + (size_t)r0 * 128 + col) =
                __floats2half2_rn(acc[i][j][0], acc[i][j][1]);
            if (r1 < M) *(__half2*)(C + (size_t)r1 * 128 + col) =
                __floats2half2_rn(acc[i][j][2], acc[i][j][3]);
        }
    }
}

// ---------------- gather aggregation (round-10 proven loop) ------------------
// out[n] = dinv[n]*( h[n]*dinv[n] + sum_{s in in(n)} h[s]*dinv[s] ) + bias
template <bool STATS, typename OutT>
__global__ void k_agg(const __half* __restrict__ h, const float* __restrict__ bias,
                      OutT* __restrict__ out) {
    __shared__ float s_sum[8][DH];
    __shared__ float s_sq[8][DH];
    int warp = threadIdx.x >> 5;
    int lane = threadIdx.x & 31;
    int n = blockIdx.x * 8 + warp;
    float4 acc = make_float4(0.f, 0.f, 0.f, 0.f);
    if (n < NNODES) {
        float di = g_dinv[n];
        {
            uint2 u = ((const uint2*)(h + (size_t)n * DH))[lane];
            float2 fa = __half22float2(*(__half2*)&u.x);
            float2 fb = __half22float2(*(__half2*)&u.y);
            acc.x = fa.x * di; acc.y = fa.y * di;
            acc.z = fb.x * di; acc.w = fb.y * di;
        }
        int beg = g_start[n], end = g_start[n + 1];
        int idx = beg;
        for (; idx + 2 <= end; idx += 2) {
            int s0 = g_src[idx], s1 = g_src[idx + 1];
            float w0 = g_dinv[s0], w1 = g_dinv[s1];
            uint2 u0 = ((const uint2*)(h + (size_t)s0 * DH))[lane];
            uint2 u1 = ((const uint2*)(h + (size_t)s1 * DH))[lane];
            float2 a0 = __half22float2(*(__half2*)&u0.x);
            float2 b0 = __half22float2(*(__half2*)&u0.y);
            float2 a1 = __half22float2(*(__half2*)&u1.x);
            float2 b1 = __half22float2(*(__half2*)&u1.y);
            acc.x = fmaf(a0.x, w0, acc.x); acc.y = fmaf(a0.y, w0, acc.y);
            acc.z = fmaf(b0.x, w0, acc.z); acc.w = fmaf(b0.y, w0, acc.w);
            acc.x = fmaf(a1.x, w1, acc.x); acc.y = fmaf(a1.y, w1, acc.y);
            acc.z = fmaf(b1.x, w1, acc.z); acc.w = fmaf(b1.y, w1, acc.w);
        }
        if (idx < end) {
            int s0 = g_src[idx];
            float w0 = g_dinv[s0];
            uint2 u0 = ((const uint2*)(h + (size_t)s0 * DH))[lane];
            float2 a0 = __half22float2(*(__half2*)&u0.x);
            float2 b0 = __half22float2(*(__half2*)&u0.y);
            acc.x = fmaf(a0.x, w0, acc.x); acc.y = fmaf(a0.y, w0, acc.y);
            acc.z = fmaf(b0.x, w0, acc.z); acc.w = fmaf(b0.y, w0, acc.w);
        }
        float4 bv = ((const float4*)bias)[lane];
        acc.x = fmaf(acc.x, di, bv.x);
        acc.y = fmaf(acc.y, di, bv.y);
        acc.z = fmaf(acc.z, di, bv.z);
        acc.w = fmaf(acc.w, di, bv.w);
        if (sizeof(OutT) == 4) {
            ((float4*)(out + (size_t)n * DH))[lane] = acc;
        } else {
            uint2 st;
            *(__half2*)&st.x = __floats2half2_rn(acc.x, acc.y);
            *(__half2*)&st.y = __floats2half2_rn(acc.z, acc.w);
            ((uint2*)(out + (size_t)n * DH))[lane] = st;
        }
    }
    if (STATS) {
        int c = lane * 4;
        s_sum[warp][c + 0] = acc.x; s_sum[warp][c + 1] = acc.y;
        s_sum[warp][c + 2] = acc.z; s_sum[warp][c + 3] = acc.w;
        s_sq[warp][c + 0] = acc.x * acc.x; s_sq[warp][c + 1] = acc.y * acc.y;
        s_sq[warp][c + 2] = acc.z * acc.z; s_sq[warp][c + 3] = acc.w * acc.w;
        __syncthreads();
        int t = threadIdx.x;
        int rep = blockIdx.x & (NREP - 1);
        if (t < DH) {
            float s = 0.f;
#pragma unroll
            for (int w = 0; w < 8; w++) s += s_sum[w][t];
            atomicAdd(&g_colsum_r[rep][t], s);
        } else {
            int c2 = t - DH;
            float s = 0.f;
#pragma unroll
            for (int w = 0; w < 8; w++) s += s_sq[w][c2];
            atomicAdd(&g_colsq_r[rep][c2], s);
        }
    }
}

// ---------------- BN stats: reduce replicas -> scale/shift --------------------
__global__ void k_bnstats(const float* __restrict__ gamma, const float* __restrict__ beta) {
    int t = threadIdx.x;
    float sum = 0.f, sq = 0.f;
#pragma unroll
    for (int r = 0; r < NREP; r++) { sum += g_colsum_r[r][t]; sq += g_colsq_r[r][t]; }
    float mean = sum * (1.0f / NNODES);
    float var = sq * (1.0f / NNODES) - mean * mean;
    float inv = rsqrtf(var + 1e-5f);
    float sc = gamma[t] * inv;
    g_scale[t] = sc;
    g_shift[t] = beta[t] - mean * sc;
}

// ---------------- launch -----------------------------------------------------
extern "C" void kernel_launch(void* const* d_in, const int* in_sizes, int n_in,
                              void* d_out, int out_size) {
    const float* x     = (const float*)d_in[0];
    const int*   ei    = (const int*)d_in[1];
    const float* W1    = (const float*)d_in[2];
    const float* b1    = (const float*)d_in[3];
    const float* gamma = (const float*)d_in[4];
    const float* beta  = (const float*)d_in[5];
    const float* W2    = (const float*)d_in[6];
    const float* b2    = (const float*)d_in[7];
    float*       out   = (float*)d_out;

    __half* h   = nullptr; cudaGetSymbolAddress((void**)&h,   g_h);
    __half* agg = nullptr; cudaGetSymbolAddress((void**)&agg, g_agg16);
    __half* w1t = nullptr; cudaGetSymbolAddress((void**)&w1t, g_w1t);
    __half* w2t = nullptr; cudaGetSymbolAddress((void**)&w2t, g_w2t);

    static cudaStream_t s2 = nullptr;
    static cudaEvent_t ev_fork = nullptr, ev_join = nullptr;
    if (s2 == nullptr) {
        cudaStreamCreateWithFlags(&s2, cudaStreamNonBlocking);
        cudaEventCreateWithFlags(&ev_fork, cudaEventDisableTiming);
        cudaEventCreateWithFlags(&ev_join, cudaEventDisableTiming);
    }

    // fork: CSR build (depends only on edge_index) concurrent with wprep+GEMM1
    cudaEventRecord(ev_fork, 0);
    cudaStreamWaitEvent(s2, ev_fork, 0);

    k_init<<<(NNODES + 255) / 256, 256, 0, s2>>>();
    k_count<<<(NEDGES / 4 + 255) / 256, 256, 0, s2>>>(ei);
    k_scan1<<<NSCAN_BLOCKS, SCAN_CHUNK, 0, s2>>>();
    k_scan3<<<(NNODES + 255) / 256, 256, 0, s2>>>();
    k_buildcsr<<<(NEDGES + 255) / 256, 256, 0, s2>>>(ei);

    k_wprep<<<(DH * DH + 255) / 256, 256>>>(W1, W2);
    k_gemm<float, false><<<(NNODES + 127) / 128, 256>>>(x, w1t, h, NNODES);

    cudaEventRecord(ev_join, s2);
    cudaStreamWaitEvent(0, ev_join, 0);

    // layer 1: aggregate(+colstats, fp16 out) -> BN params
    k_agg<true, __half><<<(NNODES + 7) / 8, 256>>>(h, b1, agg);
    k_bnstats<<<1, DH>>>(gamma, beta);

    // layer 2: GEMM(fp16 HMMA, fused BN+ReLU on A) -> aggregate -> d_out
    k_gemm<__half, true><<<(NNODES + 127) / 128, 256>>>(agg, w2t, h, NNODES);
    k_agg<false, float><<<(NNODES + 7) / 8, 256>>>(h, b2, out);
}